// round 1
// baseline (speedup 1.0000x reference)
#include <cuda_runtime.h>
#include <cuda_bf16.h>
#include <cstdint>
#include <math.h>

// Problem constants
constexpr int NB  = 4;     // batch
constexpr int NN  = 2048;  // nodes
constexpr int IND = 256;   // in_dim
constexpr int NH  = 4;     // heads
constexpr int OD  = 64;    // out_dim per head
constexpr int OUT_ELEMS = NB * NN * IND;        // 2,097,152 (out tensor)
// d_out layout: [out (B,N,H*OD)] then [b_inv (B,H,N,N)]

// Scratch: per (b,n) row of 512: cols [0,256) = gate (post-sigmoid),
// cols [256,512) = h values laid out head-major (h*64 + o).
__device__ float g_pre[(size_t)NB * NN * 512];

// ---------- packed f32x2 helpers ----------
__device__ __forceinline__ unsigned long long pack2(float lo, float hi) {
    unsigned long long r;
    asm("mov.b64 %0, {%1, %2};" : "=l"(r) : "r"(__float_as_uint(lo)), "r"(__float_as_uint(hi)));
    return r;
}
__device__ __forceinline__ void unpack2(unsigned long long v, float& lo, float& hi) {
    unsigned int a, b;
    asm("mov.b64 {%0, %1}, %2;" : "=r"(a), "=r"(b) : "l"(v));
    lo = __uint_as_float(a); hi = __uint_as_float(b);
}
__device__ __forceinline__ void fma2(unsigned long long& d, unsigned long long a, unsigned long long b) {
    asm("fma.rn.f32x2 %0, %1, %2, %0;" : "+l"(d) : "l"(a), "l"(b));
}

// =====================================================================
// Kernel 1: fused pre-GEMM  C[8192,512] = feat[8192,256] @ Mcomb[256,512]
//   Mcomb[k, j<256]   = Hw[j,k]        (gate logits; epilogue: sigmoid(+Hb))
//   Mcomb[k, 256+h*64+o] = W[h,k,o]    (h values; stored raw)
// Tiles: 64x64, 256 threads, thread tile 4x4, K-chunk 32.
// =====================================================================
__global__ __launch_bounds__(256) void k_pre(
    const float* __restrict__ feat, const float* __restrict__ W,
    const float* __restrict__ Hw,   const float* __restrict__ Hb)
{
    __shared__ float As[32][68];   // [k][m], padded to reduce store conflicts
    __shared__ float Bs[32][64];   // [k][j]

    const int tid = threadIdx.x;
    const int tx = tid & 15, ty = tid >> 4;
    const int m0 = blockIdx.x * 64;
    const int j0 = blockIdx.y * 64;

    unsigned long long acc[4][2];
#pragma unroll
    for (int i = 0; i < 4; i++) { acc[i][0] = 0ull; acc[i][1] = 0ull; }

    for (int k0 = 0; k0 < IND; k0 += 32) {
        // ---- A tile: feat rows m0..m0+63, k k0..k0+31, store transposed ----
#pragma unroll
        for (int l = 0; l < 2; l++) {
            int idx = tid + l * 256;
            int r = idx >> 3, c4 = (idx & 7) << 2;
            float4 v = *(const float4*)&feat[(size_t)(m0 + r) * IND + k0 + c4];
            As[c4 + 0][r] = v.x; As[c4 + 1][r] = v.y;
            As[c4 + 2][r] = v.z; As[c4 + 3][r] = v.w;
        }
        // ---- B tile ----
        if (j0 < 256) {
            // gate region: B[k][j] = Hw[j, k] (row-major Hw, contiguous in k)
#pragma unroll
            for (int l = 0; l < 2; l++) {
                int idx = tid + l * 256;
                int r = idx >> 3, c4 = (idx & 7) << 2;  // r: j-offset, c4: k-offset
                float4 v = *(const float4*)&Hw[(size_t)(j0 + r) * IND + k0 + c4];
                Bs[c4 + 0][r] = v.x; Bs[c4 + 1][r] = v.y;
                Bs[c4 + 2][r] = v.z; Bs[c4 + 3][r] = v.w;
            }
        } else {
            // h region: B[k][o] = W[head][k][o], contiguous in o
            const int hh = (j0 - 256) >> 6;
            const float* Wb = W + (size_t)hh * IND * OD;
#pragma unroll
            for (int l = 0; l < 2; l++) {
                int idx = tid + l * 256;
                int kk = idx >> 4, o4 = (idx & 15) << 2;
                float4 v = *(const float4*)&Wb[(size_t)(k0 + kk) * OD + o4];
                *(float4*)&Bs[kk][o4] = v;
            }
        }
        __syncthreads();

#pragma unroll
        for (int k = 0; k < 32; k++) {
            float4 a  = *(const float4*)&As[k][ty << 2];
            float4 bv = *(const float4*)&Bs[k][tx << 2];
            unsigned long long bp0 = pack2(bv.x, bv.y);
            unsigned long long bp1 = pack2(bv.z, bv.w);
            float av[4] = {a.x, a.y, a.z, a.w};
#pragma unroll
            for (int i = 0; i < 4; i++) {
                unsigned long long ad = pack2(av[i], av[i]);
                fma2(acc[i][0], ad, bp0);
                fma2(acc[i][1], ad, bp1);
            }
        }
        __syncthreads();
    }

    // ---- epilogue: sigmoid(+Hb) for gate cols, raw for h cols ----
    const bool is_gate = (j0 < 256);
#pragma unroll
    for (int i = 0; i < 4; i++) {
        int m = m0 + (ty << 2) + i;
#pragma unroll
        for (int jp = 0; jp < 2; jp++) {
            float c0, c1;
            unpack2(acc[i][jp], c0, c1);
            float cv[2] = {c0, c1};
#pragma unroll
            for (int q = 0; q < 2; q++) {
                int j = j0 + (tx << 2) + jp * 2 + q;
                float v = cv[q];
                if (is_gate) v = 1.0f / (1.0f + expf(-(v + Hb[j])));
                g_pre[(size_t)m * 512 + j] = v;
            }
        }
    }
}

// =====================================================================
// Kernel 2: per-(b,h)  feat_out[2048,64] = IB[b,h] @ h[b,h]
//   - A-tile loads write-through copy IB -> d_out's b_inv region
//   - epilogue: +bias, elu, sigmoid-gate blend, store out slice
// Tiles: 64 rows x 64 cols (full N), 256 threads, 4x4 thread tile, K-chunk 32.
// =====================================================================
__global__ __launch_bounds__(256) void k_main(
    const float* __restrict__ IB, const float* __restrict__ feat,
    const float* __restrict__ bias, float* __restrict__ out)
{
    __shared__ float As[32][68];
    __shared__ float Bs[32][64];

    const int tid = threadIdx.x;
    const int tx = tid & 15, ty = tid >> 4;
    const int r0 = blockIdx.x * 64;
    const int bh = blockIdx.y;
    const int bb = bh >> 2, hh = bh & 3;

    const float* Abase = IB + (size_t)bh * NN * NN;
    float* copy_base   = out + OUT_ELEMS + (size_t)bh * NN * NN;
    // B[k][o] = g_pre[(bb*NN + k)*512 + 256 + hh*64 + o]
    const float* Bbase = g_pre + (size_t)bb * NN * 512 + 256 + hh * 64;

    unsigned long long acc[4][2];
#pragma unroll
    for (int i = 0; i < 4; i++) { acc[i][0] = 0ull; acc[i][1] = 0ull; }

    for (int k0 = 0; k0 < NN; k0 += 32) {
        // ---- A tile + write-through copy of IB into b_inv output ----
#pragma unroll
        for (int l = 0; l < 2; l++) {
            int idx = tid + l * 256;
            int r = idx >> 3, c4 = (idx & 7) << 2;
            size_t goff = (size_t)(r0 + r) * NN + k0 + c4;
            float4 v = *(const float4*)&Abase[goff];
            *(float4*)&copy_base[goff] = v;
            As[c4 + 0][r] = v.x; As[c4 + 1][r] = v.y;
            As[c4 + 2][r] = v.z; As[c4 + 3][r] = v.w;
        }
        // ---- B tile (64 contiguous floats per row, stride 512) ----
#pragma unroll
        for (int l = 0; l < 2; l++) {
            int idx = tid + l * 256;
            int kk = idx >> 4, o4 = (idx & 15) << 2;
            float4 v = *(const float4*)&Bbase[(size_t)(k0 + kk) * 512 + o4];
            *(float4*)&Bs[kk][o4] = v;
        }
        __syncthreads();

#pragma unroll
        for (int k = 0; k < 32; k++) {
            float4 a  = *(const float4*)&As[k][ty << 2];
            float4 bv = *(const float4*)&Bs[k][tx << 2];
            unsigned long long bp0 = pack2(bv.x, bv.y);
            unsigned long long bp1 = pack2(bv.z, bv.w);
            float av[4] = {a.x, a.y, a.z, a.w};
#pragma unroll
            for (int i = 0; i < 4; i++) {
                unsigned long long ad = pack2(av[i], av[i]);
                fma2(acc[i][0], ad, bp0);
                fma2(acc[i][1], ad, bp1);
            }
        }
        __syncthreads();
    }

    // ---- epilogue: bias + elu + gate blend ----
#pragma unroll
    for (int i = 0; i < 4; i++) {
        int n = r0 + (ty << 2) + i;
        size_t row = (size_t)bb * NN + n;
#pragma unroll
        for (int jp = 0; jp < 2; jp++) {
            float c0, c1;
            unpack2(acc[i][jp], c0, c1);
            float cv[2] = {c0, c1};
#pragma unroll
            for (int q = 0; q < 2; q++) {
                int o = (tx << 2) + jp * 2 + q;
                float v = cv[q] + bias[o];
                float e = (v > 0.0f) ? v : expm1f(v);
                int c = hh * OD + o;                       // out column in [0,256)
                float g  = g_pre[row * 512 + c];           // gate
                float fi = feat[row * IND + c];            // residual
                out[row * IND + c] = g * e + (1.0f - g) * fi;
            }
        }
    }
}

extern "C" void kernel_launch(void* const* d_in, const int* in_sizes, int n_in,
                              void* d_out, int out_size)
{
    const float* feat = (const float*)d_in[0];  // [4,2048,256]
    const float* IB   = (const float*)d_in[1];  // [4,4,2048,2048]
    const float* W    = (const float*)d_in[2];  // [4,256,64]
    const float* bias = (const float*)d_in[3];  // [64]
    const float* Hw   = (const float*)d_in[4];  // [256,256]
    const float* Hb   = (const float*)d_in[5];  // [256]
    float* out = (float*)d_out;

    // Kernel 1: gate + h   (grid: 8192/64 x 512/64)
    dim3 g1(NB * NN / 64, 512 / 64);
    k_pre<<<g1, 256>>>(feat, W, Hw, Hb);

    // Kernel 2: 16 (b,h) GEMMs + IB copy + fused epilogue (grid: 2048/64 x 16)
    dim3 g2(NN / 64, NB * NH);
    k_main<<<g2, 256>>>(IB, feat, bias, out);
}

// round 3
// speedup vs baseline: 1.5862x; 1.5862x over previous
#include <cuda_runtime.h>
#include <cuda_bf16.h>
#include <cstdint>
#include <math.h>

// Problem constants
constexpr int NB  = 4;     // batch
constexpr int NN  = 2048;  // nodes
constexpr int IND = 256;   // in_dim
constexpr int NH  = 4;     // heads
constexpr int OD  = 64;    // out_dim per head
constexpr int OUT_ELEMS = NB * NN * IND;
// d_out layout: [out (B,N,H*OD)] then [b_inv (B,H,N,N)]

// Scratch: per (b,n) row of 512: cols [0,256) = gate (post-sigmoid),
// cols [256,512) = h values (head-major h*64+o). h region is [k][o]-contiguous.
__device__ float g_pre[(size_t)NB * NN * 512];

// ====================== helpers ======================
__device__ __forceinline__ uint32_t smem_to_u32(const void* p) {
    uint32_t a;
    asm("{ .reg .u64 t; cvta.to.shared.u64 t, %1; cvt.u32.u64 %0, t; }" : "=r"(a) : "l"(p));
    return a;
}

// fp32 -> (bf16 hi, bf16 lo) split, packing two consecutive elements per word
__device__ __forceinline__ void split2(float x0, float x1, uint32_t& hi, uint32_t& lo) {
    __nv_bfloat16 h0 = __float2bfloat16(x0), h1 = __float2bfloat16(x1);
    hi = (uint32_t)__bfloat16_as_ushort(h0) | ((uint32_t)__bfloat16_as_ushort(h1) << 16);
    float r0 = x0 - __bfloat162float(h0), r1 = x1 - __bfloat162float(h1);
    __nv_bfloat16 l0 = __float2bfloat16(r0), l1 = __float2bfloat16(r1);
    lo = (uint32_t)__bfloat16_as_ushort(l0) | ((uint32_t)__bfloat16_as_ushort(l1) << 16);
}

__device__ __forceinline__ void ldsm_x4(uint32_t r[4], uint32_t addr) {
    asm volatile("ldmatrix.sync.aligned.m8n8.x4.shared.b16 {%0,%1,%2,%3}, [%4];"
        : "=r"(r[0]), "=r"(r[1]), "=r"(r[2]), "=r"(r[3]) : "r"(addr));
}
__device__ __forceinline__ void ldsm_x4t(uint32_t r[4], uint32_t addr) {
    asm volatile("ldmatrix.sync.aligned.m8n8.x4.trans.shared.b16 {%0,%1,%2,%3}, [%4];"
        : "=r"(r[0]), "=r"(r[1]), "=r"(r[2]), "=r"(r[3]) : "r"(addr));
}
__device__ __forceinline__ void mma_bf16(float c[4], const uint32_t a[4], uint32_t b0, uint32_t b1) {
    asm volatile("mma.sync.aligned.m16n8k16.row.col.f32.bf16.bf16.f32 "
        "{%0,%1,%2,%3}, {%4,%5,%6,%7}, {%8,%9}, {%0,%1,%2,%3};"
        : "+f"(c[0]), "+f"(c[1]), "+f"(c[2]), "+f"(c[3])
        : "r"(a[0]), "r"(a[1]), "r"(a[2]), "r"(a[3]), "r"(b0), "r"(b1));
}
#define SWZ(byte) ((byte) ^ (((byte) >> 3) & 0x70))

// ---------- packed f32x2 helpers (k_pre) ----------
__device__ __forceinline__ unsigned long long pack2(float lo, float hi) {
    unsigned long long r;
    asm("mov.b64 %0, {%1, %2};" : "=l"(r) : "r"(__float_as_uint(lo)), "r"(__float_as_uint(hi)));
    return r;
}
__device__ __forceinline__ void unpack2(unsigned long long v, float& lo, float& hi) {
    unsigned int a, b;
    asm("mov.b64 {%0, %1}, %2;" : "=r"(a), "=r"(b) : "l"(v));
    lo = __uint_as_float(a); hi = __uint_as_float(b);
}
__device__ __forceinline__ void fma2(unsigned long long& d, unsigned long long a, unsigned long long b) {
    asm("fma.rn.f32x2 %0, %1, %2, %0;" : "+l"(d) : "l"(a), "l"(b));
}

// =====================================================================
// Kernel 1: fused pre-GEMM  C[8192,512] = feat[8192,256] @ Mcomb[256,512]
// =====================================================================
__global__ __launch_bounds__(256) void k_pre(
    const float* __restrict__ feat, const float* __restrict__ W,
    const float* __restrict__ Hw,   const float* __restrict__ Hb)
{
    __shared__ float As[32][68];
    __shared__ float Bs[32][64];

    const int tid = threadIdx.x;
    const int tx = tid & 15, ty = tid >> 4;
    const int m0 = blockIdx.x * 64;
    const int j0 = blockIdx.y * 64;

    unsigned long long acc[4][2];
#pragma unroll
    for (int i = 0; i < 4; i++) { acc[i][0] = 0ull; acc[i][1] = 0ull; }

    for (int k0 = 0; k0 < IND; k0 += 32) {
#pragma unroll
        for (int l = 0; l < 2; l++) {
            int idx = tid + l * 256;
            int r = idx >> 3, c4 = (idx & 7) << 2;
            float4 v = *(const float4*)&feat[(size_t)(m0 + r) * IND + k0 + c4];
            As[c4 + 0][r] = v.x; As[c4 + 1][r] = v.y;
            As[c4 + 2][r] = v.z; As[c4 + 3][r] = v.w;
        }
        if (j0 < 256) {
#pragma unroll
            for (int l = 0; l < 2; l++) {
                int idx = tid + l * 256;
                int r = idx >> 3, c4 = (idx & 7) << 2;
                float4 v = *(const float4*)&Hw[(size_t)(j0 + r) * IND + k0 + c4];
                Bs[c4 + 0][r] = v.x; Bs[c4 + 1][r] = v.y;
                Bs[c4 + 2][r] = v.z; Bs[c4 + 3][r] = v.w;
            }
        } else {
            const int hh = (j0 - 256) >> 6;
            const float* Wb = W + (size_t)hh * IND * OD;
#pragma unroll
            for (int l = 0; l < 2; l++) {
                int idx = tid + l * 256;
                int kk = idx >> 4, o4 = (idx & 15) << 2;
                float4 v = *(const float4*)&Wb[(size_t)(k0 + kk) * OD + o4];
                *(float4*)&Bs[kk][o4] = v;
            }
        }
        __syncthreads();

#pragma unroll
        for (int k = 0; k < 32; k++) {
            float4 a  = *(const float4*)&As[k][ty << 2];
            float4 bv = *(const float4*)&Bs[k][tx << 2];
            unsigned long long bp0 = pack2(bv.x, bv.y);
            unsigned long long bp1 = pack2(bv.z, bv.w);
            float av[4] = {a.x, a.y, a.z, a.w};
#pragma unroll
            for (int i = 0; i < 4; i++) {
                unsigned long long ad = pack2(av[i], av[i]);
                fma2(acc[i][0], ad, bp0);
                fma2(acc[i][1], ad, bp1);
            }
        }
        __syncthreads();
    }

    const bool is_gate = (j0 < 256);
#pragma unroll
    for (int i = 0; i < 4; i++) {
        int m = m0 + (ty << 2) + i;
#pragma unroll
        for (int jp = 0; jp < 2; jp++) {
            float c0, c1;
            unpack2(acc[i][jp], c0, c1);
            float cv[2] = {c0, c1};
#pragma unroll
            for (int q = 0; q < 2; q++) {
                int j = j0 + (tx << 2) + jp * 2 + q;
                float v = cv[q];
                if (is_gate) v = 1.0f / (1.0f + expf(-(v + Hb[j])));
                g_pre[(size_t)m * 512 + j] = v;
            }
        }
    }
}

// =====================================================================
// Kernel 2: HMMA (mma.sync bf16 hi/lo 3-pass) per (b,h): C[2048,64] = IB @ h
//   CTA: 128 rows x 64 cols, 8 warps (warp tile 32x32), K-chunk 64,
//   double-buffered swizzled SMEM, register-prefetched LDG,
//   IB write-through copy fused in staging, elu/gate epilogue.
// SMEM stage (48KB): A_hi[128][64]bf16 | A_lo | B_hi[64][64]bf16 | B_lo
// =====================================================================
constexpr int STAGE = 49152;
constexpr int SMEM_DYN = 2 * STAGE + 128;

__global__ __launch_bounds__(256) void k_main_mma(
    const float* __restrict__ IB, const float* __restrict__ feat,
    const float* __restrict__ bias, float* __restrict__ out)
{
    extern __shared__ char dsm_raw[];
    char* sm = (char*)(((uintptr_t)dsm_raw + 127) & ~(uintptr_t)127);
    const uint32_t smu = smem_to_u32(sm);

    const int tid = threadIdx.x;
    const int lane = tid & 31, wid = tid >> 5;
    const int r0 = blockIdx.x * 128;
    const int bh = blockIdx.y, bb = bh >> 2, hh = bh & 3;

    const float* A  = IB + (size_t)bh * NN * NN + (size_t)r0 * NN;
    float* Acopy    = out + OUT_ELEMS + (size_t)bh * NN * NN + (size_t)r0 * NN;
    const float* Bsrc = g_pre + (size_t)bb * NN * 512 + 256 + hh * 64;  // [k][o], stride 512

    // staging thread mappings
    const int arow = tid >> 4;            // 0..15 (rows arow+16j, j<8)
    const int acol = (tid & 15) << 2;     // fp32 col within chunk
    const int brow = tid >> 2;            // 0..63
    const int bcol = (tid & 3) << 4;      // fp32 col base (4x float4)

    uint32_t saoff[8];
#pragma unroll
    for (int j = 0; j < 8; j++) {
        uint32_t b = (uint32_t)(arow + 16 * j) * 128 + (uint32_t)acol * 2;
        saoff[j] = SWZ(b);
    }
    uint32_t sboff[4];
#pragma unroll
    for (int q = 0; q < 4; q++) {
        uint32_t b = (uint32_t)brow * 128 + (uint32_t)(bcol + 4 * q) * 2;
        sboff[q] = SWZ(b);
    }

    // prologue: load chunk 0
    float4 ar[8], br[4];
#pragma unroll
    for (int j = 0; j < 8; j++)
        ar[j] = *(const float4*)&A[(size_t)(arow + 16 * j) * NN + acol];
#pragma unroll
    for (int q = 0; q < 4; q++)
        br[q] = *(const float4*)&Bsrc[(size_t)brow * 512 + bcol + 4 * q];

    float acc[2][4][4];
#pragma unroll
    for (int mi = 0; mi < 2; mi++)
#pragma unroll
        for (int ni = 0; ni < 4; ni++)
#pragma unroll
            for (int r = 0; r < 4; r++) acc[mi][ni][r] = 0.0f;

    const int m_w = (wid >> 1) * 32;
    const int n_w = (wid & 1) * 32;

    // precomputed LDSM lane addressing pieces
    const int a_row_l = (lane & 15);                 // + m_w + mi*16
    const int a_colb  = ((lane >> 4) << 3) * 2;      // byte offset of 8-col group
    const int b_krow  = (lane & 7) + ((lane >> 3) & 1) * 8;  // + ks*16
    const int b_ncol  = ((lane >> 4) << 3);          // + n_w + nj*16

    for (int c = 0; c < 32; c++) {
        char* buf = sm + (c & 1) * STAGE;
        const uint32_t bufu = smu + (c & 1) * STAGE;
        const int k0 = c * 64;

        __syncthreads();

        // ---- stage A: write-through copy + bf16 split STS ----
#pragma unroll
        for (int j = 0; j < 8; j++) {
            *(float4*)&Acopy[(size_t)(arow + 16 * j) * NN + k0 + acol] = ar[j];
            uint32_t h0, l0, h1, l1;
            split2(ar[j].x, ar[j].y, h0, l0);
            split2(ar[j].z, ar[j].w, h1, l1);
            *(uint2*)(buf + saoff[j])         = make_uint2(h0, h1);
            *(uint2*)(buf + 16384 + saoff[j]) = make_uint2(l0, l1);
        }
        // ---- stage B ----
#pragma unroll
        for (int q = 0; q < 4; q++) {
            uint32_t h0, l0, h1, l1;
            split2(br[q].x, br[q].y, h0, l0);
            split2(br[q].z, br[q].w, h1, l1);
            *(uint2*)(buf + 32768 + sboff[q]) = make_uint2(h0, h1);
            *(uint2*)(buf + 40960 + sboff[q]) = make_uint2(l0, l1);
        }
        __syncthreads();

        // ---- prefetch next chunk ----
        if (c < 31) {
            const int kn = k0 + 64;
#pragma unroll
            for (int j = 0; j < 8; j++)
                ar[j] = *(const float4*)&A[(size_t)(arow + 16 * j) * NN + kn + acol];
#pragma unroll
            for (int q = 0; q < 4; q++)
                br[q] = *(const float4*)&Bsrc[(size_t)(kn + brow) * 512 + bcol + 4 * q];
        }

        // ---- compute: 4 k16 steps ----
#pragma unroll
        for (int ks = 0; ks < 4; ks++) {
            uint32_t ah[2][4], al[2][4], bhf[2][4], blf[2][4];
#pragma unroll
            for (int mi = 0; mi < 2; mi++) {
                uint32_t byte = (uint32_t)(m_w + mi * 16 + a_row_l) * 128 + (uint32_t)(ks * 32) + a_colb;
                uint32_t sw = SWZ(byte);
                ldsm_x4(ah[mi], bufu + sw);
                ldsm_x4(al[mi], bufu + 16384 + sw);
            }
#pragma unroll
            for (int nj = 0; nj < 2; nj++) {
                uint32_t byte = (uint32_t)(ks * 16 + b_krow) * 128 + (uint32_t)(n_w + nj * 16 + b_ncol) * 2;
                uint32_t sw = SWZ(byte);
                ldsm_x4t(bhf[nj], bufu + 32768 + sw);
                ldsm_x4t(blf[nj], bufu + 40960 + sw);
            }
#pragma unroll
            for (int mi = 0; mi < 2; mi++)
#pragma unroll
                for (int ni = 0; ni < 4; ni++) {
                    const int j = ni >> 1, p = (ni & 1) << 1;
                    mma_bf16(acc[mi][ni], ah[mi], bhf[j][p], bhf[j][p + 1]);
                    mma_bf16(acc[mi][ni], ah[mi], blf[j][p], blf[j][p + 1]);
                    mma_bf16(acc[mi][ni], al[mi], bhf[j][p], bhf[j][p + 1]);
                }
        }
    }

    // ---- epilogue: bias + elu + sigmoid-gate blend ----
#pragma unroll
    for (int mi = 0; mi < 2; mi++) {
#pragma unroll
        for (int rr = 0; rr < 2; rr++) {
            const int nrow = r0 + m_w + mi * 16 + (lane >> 2) + rr * 8;
            const size_t row = (size_t)bb * NN + nrow;
#pragma unroll
            for (int ni = 0; ni < 4; ni++) {
                const int col = n_w + ni * 8 + ((lane & 3) << 1);
                const int cg = hh * 64 + col;
                float v0 = acc[mi][ni][rr * 2 + 0] + __ldg(&bias[col]);
                float v1 = acc[mi][ni][rr * 2 + 1] + __ldg(&bias[col + 1]);
                float e0 = (v0 > 0.0f) ? v0 : expm1f(v0);
                float e1 = (v1 > 0.0f) ? v1 : expm1f(v1);
                float2 g2 = *(const float2*)&g_pre[row * 512 + cg];
                float2 f2 = *(const float2*)&feat[row * IND + cg];
                float2 o2;
                o2.x = g2.x * e0 + (1.0f - g2.x) * f2.x;
                o2.y = g2.y * e1 + (1.0f - g2.y) * f2.y;
                *(float2*)&out[row * IND + cg] = o2;
            }
        }
    }
}

extern "C" void kernel_launch(void* const* d_in, const int* in_sizes, int n_in,
                              void* d_out, int out_size)
{
    const float* feat = (const float*)d_in[0];  // [4,2048,256]
    const float* IB   = (const float*)d_in[1];  // [4,4,2048,2048]
    const float* W    = (const float*)d_in[2];  // [4,256,64]
    const float* bias = (const float*)d_in[3];  // [64]
    const float* Hw   = (const float*)d_in[4];  // [256,256]
    const float* Hb   = (const float*)d_in[5];  // [256]
    float* out = (float*)d_out;

    // Kernel 1: gate + h
    dim3 g1(NB * NN / 64, 512 / 64);
    k_pre<<<g1, 256>>>(feat, W, Hw, Hb);

    // Kernel 2: HMMA main GEMM + IB copy + fused epilogue
    cudaFuncSetAttribute(k_main_mma, cudaFuncAttributeMaxDynamicSharedMemorySize, SMEM_DYN);
    dim3 g2(NN / 128, NB * NH);
    k_main_mma<<<g2, 256, SMEM_DYN>>>(IB, feat, bias, out);
}

// round 4
// speedup vs baseline: 2.1695x; 1.3678x over previous
#include <cuda_runtime.h>
#include <cuda_bf16.h>
#include <cstdint>
#include <math.h>

// Problem constants
constexpr int NB  = 4;     // batch
constexpr int NN  = 2048;  // nodes
constexpr int IND = 256;   // in_dim
constexpr int NH  = 4;     // heads
constexpr int OD  = 64;    // out_dim per head
constexpr int OUT_ELEMS = NB * NN * IND;
// d_out layout: [out (B,N,H*OD)] then [b_inv (B,H,N,N)]

// Scratch
__device__ float g_pre[(size_t)NB * NN * 512];              // gate [0,256) + h [256,512)
__device__ __nv_bfloat16 g_BT_hi[512 * IND];                // B^T for k_pre: [j][k]
__device__ __nv_bfloat16 g_BT_lo[512 * IND];

// ====================== helpers ======================
__device__ __forceinline__ uint32_t smem_to_u32(const void* p) {
    uint32_t a;
    asm("{ .reg .u64 t; cvta.to.shared.u64 t, %1; cvt.u32.u64 %0, t; }" : "=r"(a) : "l"(p));
    return a;
}
__device__ __forceinline__ void split2(float x0, float x1, uint32_t& hi, uint32_t& lo) {
    __nv_bfloat16 h0 = __float2bfloat16(x0), h1 = __float2bfloat16(x1);
    hi = (uint32_t)__bfloat16_as_ushort(h0) | ((uint32_t)__bfloat16_as_ushort(h1) << 16);
    float r0 = x0 - __bfloat162float(h0), r1 = x1 - __bfloat162float(h1);
    __nv_bfloat16 l0 = __float2bfloat16(r0), l1 = __float2bfloat16(r1);
    lo = (uint32_t)__bfloat16_as_ushort(l0) | ((uint32_t)__bfloat16_as_ushort(l1) << 16);
}
__device__ __forceinline__ void ldsm_x4(uint32_t r[4], uint32_t addr) {
    asm volatile("ldmatrix.sync.aligned.m8n8.x4.shared.b16 {%0,%1,%2,%3}, [%4];"
        : "=r"(r[0]), "=r"(r[1]), "=r"(r[2]), "=r"(r[3]) : "r"(addr));
}
__device__ __forceinline__ void ldsm_x4t(uint32_t r[4], uint32_t addr) {
    asm volatile("ldmatrix.sync.aligned.m8n8.x4.trans.shared.b16 {%0,%1,%2,%3}, [%4];"
        : "=r"(r[0]), "=r"(r[1]), "=r"(r[2]), "=r"(r[3]) : "r"(addr));
}
__device__ __forceinline__ void mma_bf16(float c[4], const uint32_t a[4], uint32_t b0, uint32_t b1) {
    asm volatile("mma.sync.aligned.m16n8k16.row.col.f32.bf16.bf16.f32 "
        "{%0,%1,%2,%3}, {%4,%5,%6,%7}, {%8,%9}, {%0,%1,%2,%3};"
        : "+f"(c[0]), "+f"(c[1]), "+f"(c[2]), "+f"(c[3])
        : "r"(a[0]), "r"(a[1]), "r"(a[2]), "r"(a[3]), "r"(b0), "r"(b1));
}
#define SWZ128(b) ((b) ^ (((b) >> 3) & 0x70))
#define SWZ64(b)  ((b) ^ (((b) >> 3) & 0x30))

// SMEM stage layout (both GEMM kernels), K-chunk 32:
//   A_hi [128][32] bf16 @ 0      (8KB, 64B rows, SW64)
//   A_lo                @ 8192
//   B_hi [*][32|64]     @ 16384  (4KB)
//   B_lo                @ 20480
constexpr int STAGE = 24576;
constexpr int SMEM_DYN = 2 * STAGE + 128;

// =====================================================================
// Prep: build B^T (bf16 hi/lo) for k_pre.  j<256: Hw[j][k]; j>=256: W[h][k][o]
// =====================================================================
__global__ void k_prep(const float* __restrict__ Hw, const float* __restrict__ W)
{
    const int j = blockIdx.x;
    const int k = threadIdx.x;
    float v;
    if (j < 256) v = Hw[(size_t)j * IND + k];
    else {
        int jj = j - 256, h = jj >> 6, o = jj & 63;
        v = W[((size_t)h * IND + k) * OD + o];
    }
    __nv_bfloat16 hi = __float2bfloat16(v);
    __nv_bfloat16 lo = __float2bfloat16(v - __bfloat162float(hi));
    g_BT_hi[(size_t)j * IND + k] = hi;
    g_BT_lo[(size_t)j * IND + k] = lo;
}

// =====================================================================
// Kernel 1: HMMA pre-GEMM  C[8192,512] = feat[8192,256] @ BT^T
//   CTA 128x64, 8 warps (32x32), K-chunk 32 (8 chunks), double buffer.
//   B from g_BT (already bf16 hi/lo, row-major [j][k]) -> non-trans ldmatrix.
//   Epilogue: j<256 -> sigmoid(v+Hb[j]); else raw. Store to g_pre.
// =====================================================================
__global__ __launch_bounds__(256, 2) void k_pre(
    const float* __restrict__ feat, const float* __restrict__ Hb)
{
    extern __shared__ char dsm_raw[];
    char* sm = (char*)(((uintptr_t)dsm_raw + 127) & ~(uintptr_t)127);
    const uint32_t smu = smem_to_u32(sm);

    const int tid = threadIdx.x;
    const int lane = tid & 31, wid = tid >> 5;
    const int r0 = blockIdx.x * 128;
    const int j0 = blockIdx.y * 64;

    const float* A = feat + (size_t)r0 * IND;

    // staging maps
    const int arow = tid >> 3;           // 0..31, rows arow+32j, j<4
    const int acol = (tid & 7) << 2;     // fp32 col 0..28
    const int brow = tid >> 2;           // 0..63 (j rows)
    const int bk8  = (tid & 3) << 3;     // bf16 k offset (8 elems = 16B)

    uint32_t saoff[4];
#pragma unroll
    for (int j = 0; j < 4; j++)
        saoff[j] = SWZ64((uint32_t)(arow + 32 * j) * 64 + (uint32_t)acol * 2);
    const uint32_t sboff = SWZ64((uint32_t)brow * 64 + (uint32_t)bk8 * 2);

    float4 ar[4];
    uint4 bhr, blr;
#pragma unroll
    for (int j = 0; j < 4; j++)
        ar[j] = *(const float4*)&A[(size_t)(arow + 32 * j) * IND + acol];
    bhr = *(const uint4*)&g_BT_hi[(size_t)(j0 + brow) * IND + bk8];
    blr = *(const uint4*)&g_BT_lo[(size_t)(j0 + brow) * IND + bk8];

    float acc[2][4][4];
#pragma unroll
    for (int mi = 0; mi < 2; mi++)
#pragma unroll
        for (int ni = 0; ni < 4; ni++)
#pragma unroll
            for (int r = 0; r < 4; r++) acc[mi][ni][r] = 0.0f;

    const int m_w = (wid >> 1) * 32;
    const int n_w = (wid & 1) * 32;
    const int a_row_l = lane & 15;
    const int a_colb  = ((lane >> 4) << 3) * 2;
    const int b_row_l = (lane & 7) + ((lane >> 4) << 3);   // n row within 16-group
    const int b_kb    = (((lane >> 3) & 1) << 4);          // k byte half

    for (int c = 0; c < 8; c++) {
        char* buf = sm + (c & 1) * STAGE;
        const uint32_t bufu = smu + (c & 1) * STAGE;
        const int k0 = c * 32;

        __syncthreads();
#pragma unroll
        for (int j = 0; j < 4; j++) {
            uint32_t h0, l0, h1, l1;
            split2(ar[j].x, ar[j].y, h0, l0);
            split2(ar[j].z, ar[j].w, h1, l1);
            *(uint2*)(buf + saoff[j])        = make_uint2(h0, h1);
            *(uint2*)(buf + 8192 + saoff[j]) = make_uint2(l0, l1);
        }
        *(uint4*)(buf + 16384 + sboff) = bhr;
        *(uint4*)(buf + 20480 + sboff) = blr;
        __syncthreads();

        if (c < 7) {
            const int kn = k0 + 32;
#pragma unroll
            for (int j = 0; j < 4; j++)
                ar[j] = *(const float4*)&A[(size_t)(arow + 32 * j) * IND + kn + acol];
            bhr = *(const uint4*)&g_BT_hi[(size_t)(j0 + brow) * IND + kn + bk8];
            blr = *(const uint4*)&g_BT_lo[(size_t)(j0 + brow) * IND + kn + bk8];
        }

#pragma unroll
        for (int ks = 0; ks < 2; ks++) {
            uint32_t ah[2][4], al[2][4], bhf[2][4], blf[2][4];
#pragma unroll
            for (int mi = 0; mi < 2; mi++) {
                uint32_t sw = SWZ64((uint32_t)(m_w + mi * 16 + a_row_l) * 64 + (uint32_t)(ks * 32) + a_colb);
                ldsm_x4(ah[mi], bufu + sw);
                ldsm_x4(al[mi], bufu + 8192 + sw);
            }
#pragma unroll
            for (int nj = 0; nj < 2; nj++) {
                uint32_t sw = SWZ64((uint32_t)(n_w + nj * 16 + b_row_l) * 64 + (uint32_t)(ks * 32) + b_kb);
                ldsm_x4(bhf[nj], bufu + 16384 + sw);
                ldsm_x4(blf[nj], bufu + 20480 + sw);
            }
#pragma unroll
            for (int mi = 0; mi < 2; mi++)
#pragma unroll
                for (int ni = 0; ni < 4; ni++) {
                    const int j = ni >> 1, p = (ni & 1) << 1;
                    mma_bf16(acc[mi][ni], ah[mi], bhf[j][p], bhf[j][p + 1]);
                    mma_bf16(acc[mi][ni], ah[mi], blf[j][p], blf[j][p + 1]);
                    mma_bf16(acc[mi][ni], al[mi], bhf[j][p], bhf[j][p + 1]);
                }
        }
    }

    // epilogue
    const bool is_gate = (j0 < 256);
#pragma unroll
    for (int mi = 0; mi < 2; mi++) {
#pragma unroll
        for (int rr = 0; rr < 2; rr++) {
            const int m = r0 + m_w + mi * 16 + (lane >> 2) + rr * 8;
#pragma unroll
            for (int ni = 0; ni < 4; ni++) {
                const int j = j0 + n_w + ni * 8 + ((lane & 3) << 1);
                float v0 = acc[mi][ni][rr * 2 + 0];
                float v1 = acc[mi][ni][rr * 2 + 1];
                if (is_gate) {
                    v0 = 1.0f / (1.0f + expf(-(v0 + __ldg(&Hb[j]))));
                    v1 = 1.0f / (1.0f + expf(-(v1 + __ldg(&Hb[j + 1]))));
                }
                *(float2*)&g_pre[(size_t)m * 512 + j] = make_float2(v0, v1);
            }
        }
    }
}

// =====================================================================
// Kernel 2: HMMA main GEMM per (b,h): C[2048,64] = IB @ h
//   CTA 128x64, 8 warps (32x32), K-chunk 32 (64 chunks), double buffer,
//   2 CTAs/SM. IB write-through copy fused. elu/gate epilogue.
// =====================================================================
__global__ __launch_bounds__(256, 2) void k_main_mma(
    const float* __restrict__ IB, const float* __restrict__ feat,
    const float* __restrict__ bias, float* __restrict__ out)
{
    extern __shared__ char dsm_raw[];
    char* sm = (char*)(((uintptr_t)dsm_raw + 127) & ~(uintptr_t)127);
    const uint32_t smu = smem_to_u32(sm);

    const int tid = threadIdx.x;
    const int lane = tid & 31, wid = tid >> 5;
    const int r0 = blockIdx.x * 128;
    const int bh = blockIdx.y, bb = bh >> 2, hh = bh & 3;

    const float* A   = IB + (size_t)bh * NN * NN + (size_t)r0 * NN;
    float* Acopy     = out + OUT_ELEMS + (size_t)bh * NN * NN + (size_t)r0 * NN;
    const float* Bsrc = g_pre + (size_t)bb * NN * 512 + 256 + hh * 64;  // [k][o] stride 512

    // staging maps
    const int arow = tid >> 3;           // 0..31, rows arow+32j, j<4
    const int acol = (tid & 7) << 2;     // fp32 col 0..28
    const int brow = tid >> 3;           // 0..31 (k rows)
    const int bcol = (tid & 7) << 3;     // fp32 o col base (2x float4)

    uint32_t saoff[4];
#pragma unroll
    for (int j = 0; j < 4; j++)
        saoff[j] = SWZ64((uint32_t)(arow + 32 * j) * 64 + (uint32_t)acol * 2);
    const uint32_t sboff = SWZ128((uint32_t)brow * 128 + (uint32_t)bcol * 2);

    float4 ar[4], br[2];
#pragma unroll
    for (int j = 0; j < 4; j++)
        ar[j] = *(const float4*)&A[(size_t)(arow + 32 * j) * NN + acol];
    br[0] = *(const float4*)&Bsrc[(size_t)brow * 512 + bcol];
    br[1] = *(const float4*)&Bsrc[(size_t)brow * 512 + bcol + 4];

    float acc[2][4][4];
#pragma unroll
    for (int mi = 0; mi < 2; mi++)
#pragma unroll
        for (int ni = 0; ni < 4; ni++)
#pragma unroll
            for (int r = 0; r < 4; r++) acc[mi][ni][r] = 0.0f;

    const int m_w = (wid >> 1) * 32;
    const int n_w = (wid & 1) * 32;
    const int a_row_l = lane & 15;
    const int a_colb  = ((lane >> 4) << 3) * 2;
    const int b_krow  = (lane & 7) + ((lane >> 3) & 1) * 8;
    const int b_ncol  = (lane >> 4) << 3;

    for (int c = 0; c < 64; c++) {
        char* buf = sm + (c & 1) * STAGE;
        const uint32_t bufu = smu + (c & 1) * STAGE;
        const int k0 = c * 32;

        __syncthreads();
        // stage A: write-through copy + split STS
#pragma unroll
        for (int j = 0; j < 4; j++) {
            *(float4*)&Acopy[(size_t)(arow + 32 * j) * NN + k0 + acol] = ar[j];
            uint32_t h0, l0, h1, l1;
            split2(ar[j].x, ar[j].y, h0, l0);
            split2(ar[j].z, ar[j].w, h1, l1);
            *(uint2*)(buf + saoff[j])        = make_uint2(h0, h1);
            *(uint2*)(buf + 8192 + saoff[j]) = make_uint2(l0, l1);
        }
        // stage B
        {
            uint32_t h0, l0, h1, l1, h2, l2, h3, l3;
            split2(br[0].x, br[0].y, h0, l0);
            split2(br[0].z, br[0].w, h1, l1);
            split2(br[1].x, br[1].y, h2, l2);
            split2(br[1].z, br[1].w, h3, l3);
            *(uint4*)(buf + 16384 + sboff) = make_uint4(h0, h1, h2, h3);
            *(uint4*)(buf + 20480 + sboff) = make_uint4(l0, l1, l2, l3);
        }
        __syncthreads();

        if (c < 63) {
            const int kn = k0 + 32;
#pragma unroll
            for (int j = 0; j < 4; j++)
                ar[j] = *(const float4*)&A[(size_t)(arow + 32 * j) * NN + kn + acol];
            br[0] = *(const float4*)&Bsrc[(size_t)(kn + brow) * 512 + bcol];
            br[1] = *(const float4*)&Bsrc[(size_t)(kn + brow) * 512 + bcol + 4];
        }

#pragma unroll
        for (int ks = 0; ks < 2; ks++) {
            uint32_t ah[2][4], al[2][4], bhf[2][4], blf[2][4];
#pragma unroll
            for (int mi = 0; mi < 2; mi++) {
                uint32_t sw = SWZ64((uint32_t)(m_w + mi * 16 + a_row_l) * 64 + (uint32_t)(ks * 32) + a_colb);
                ldsm_x4(ah[mi], bufu + sw);
                ldsm_x4(al[mi], bufu + 8192 + sw);
            }
#pragma unroll
            for (int nj = 0; nj < 2; nj++) {
                uint32_t sw = SWZ128((uint32_t)(ks * 16 + b_krow) * 128 + (uint32_t)(n_w + nj * 16 + b_ncol) * 2);
                ldsm_x4t(bhf[nj], bufu + 16384 + sw);
                ldsm_x4t(blf[nj], bufu + 20480 + sw);
            }
#pragma unroll
            for (int mi = 0; mi < 2; mi++)
#pragma unroll
                for (int ni = 0; ni < 4; ni++) {
                    const int j = ni >> 1, p = (ni & 1) << 1;
                    mma_bf16(acc[mi][ni], ah[mi], bhf[j][p], bhf[j][p + 1]);
                    mma_bf16(acc[mi][ni], ah[mi], blf[j][p], blf[j][p + 1]);
                    mma_bf16(acc[mi][ni], al[mi], bhf[j][p], bhf[j][p + 1]);
                }
        }
    }

    // epilogue: bias + elu + sigmoid-gate blend
#pragma unroll
    for (int mi = 0; mi < 2; mi++) {
#pragma unroll
        for (int rr = 0; rr < 2; rr++) {
            const int nrow = r0 + m_w + mi * 16 + (lane >> 2) + rr * 8;
            const size_t row = (size_t)bb * NN + nrow;
#pragma unroll
            for (int ni = 0; ni < 4; ni++) {
                const int col = n_w + ni * 8 + ((lane & 3) << 1);
                const int cg = hh * 64 + col;
                float v0 = acc[mi][ni][rr * 2 + 0] + __ldg(&bias[col]);
                float v1 = acc[mi][ni][rr * 2 + 1] + __ldg(&bias[col + 1]);
                float e0 = (v0 > 0.0f) ? v0 : expm1f(v0);
                float e1 = (v1 > 0.0f) ? v1 : expm1f(v1);
                float2 g2 = *(const float2*)&g_pre[row * 512 + cg];
                float2 f2 = *(const float2*)&feat[row * IND + cg];
                float2 o2;
                o2.x = g2.x * e0 + (1.0f - g2.x) * f2.x;
                o2.y = g2.y * e1 + (1.0f - g2.y) * f2.y;
                *(float2*)&out[row * IND + cg] = o2;
            }
        }
    }
}

extern "C" void kernel_launch(void* const* d_in, const int* in_sizes, int n_in,
                              void* d_out, int out_size)
{
    const float* feat = (const float*)d_in[0];  // [4,2048,256]
    const float* IB   = (const float*)d_in[1];  // [4,4,2048,2048]
    const float* W    = (const float*)d_in[2];  // [4,256,64]
    const float* bias = (const float*)d_in[3];  // [64]
    const float* Hw   = (const float*)d_in[4];  // [256,256]
    const float* Hb   = (const float*)d_in[5];  // [256]
    float* out = (float*)d_out;

    // Prep: bf16 hi/lo B^T for k_pre
    k_prep<<<512, 256>>>(Hw, W);

    // Kernel 1: gate + h (HMMA)
    cudaFuncSetAttribute(k_pre, cudaFuncAttributeMaxDynamicSharedMemorySize, SMEM_DYN);
    dim3 g1(NB * NN / 128, 512 / 64);
    k_pre<<<g1, 256, SMEM_DYN>>>(feat, Hb);

    // Kernel 2: HMMA main GEMM + IB copy + fused epilogue
    cudaFuncSetAttribute(k_main_mma, cudaFuncAttributeMaxDynamicSharedMemorySize, SMEM_DYN);
    dim3 g2(NN / 128, NB * NH);
    k_main_mma<<<g2, 256, SMEM_DYN>>>(IB, feat, bias, out);
}